// round 6
// baseline (speedup 1.0000x reference)
#include <cuda_runtime.h>
#include <cuda_fp16.h>
#include <cstdint>

// Problem constants (fixed shapes per reference)
#define NV 100000      // vertices
#define TT 128         // temporal depth
#define EE 1600000     // edges
#define KK 9           // conv kernel
#define LL 3           // layers

// ---------------- scratch (device globals; no runtime allocation) -----------
__device__ __half g_hA[(size_t)NV * TT];   // ping  (fp16 activations)
__device__ __half g_hB[(size_t)NV * TT];   // pong
__device__ __half g_xh[(size_t)NV * TT];   // final activation (fp16, flat)
__device__ int    g_deg[NV];
__device__ int    g_fill[NV];              // fill cursor, seeded = rowptr
__device__ int    g_rowptr[NV + 1];
__device__ int    g_col[EE];

// ---------------- CSR build --------------------------------------------------
// zero degree counters AND initialize y with the output bias (independent work)
__global__ void zero_init_kernel(const float* __restrict__ bout,
                                 float* __restrict__ y) {
    int i = blockIdx.x * blockDim.x + threadIdx.x;
    if (i < NV) g_deg[i] = 0;
    if (i < TT * 3) y[i] = __ldg(&bout[i % 3]);
}

// int2-vectorized histogram over dst
__global__ void hist_kernel(const int2* __restrict__ dst2) {
    int e = blockIdx.x * blockDim.x + threadIdx.x;
    if (e < EE / 2) {
        int2 d = __ldg(&dst2[e]);
        atomicAdd(&g_deg[d.x], 1);
        atomicAdd(&g_deg[d.y], 1);
    }
}

// Single-block exclusive scan of g_deg -> g_rowptr (and seed g_fill = rowptr).
#define SB_T 1024
#define SB_CH ((NV + SB_T - 1) / SB_T)   // 98
__global__ void scan_kernel() {
    __shared__ int s[SB_T];
    int t = threadIdx.x;
    int lo = t * SB_CH;
    int hi = lo + SB_CH; if (hi > NV) hi = NV;
    int sum = 0;
    for (int i = lo; i < hi; i++) sum += g_deg[i];
    s[t] = sum;
    __syncthreads();
    for (int off = 1; off < SB_T; off <<= 1) {
        int v = (t >= off) ? s[t - off] : 0;
        __syncthreads();
        s[t] += v;
        __syncthreads();
    }
    int run = s[t] - sum;   // exclusive prefix of this thread's chunk
    for (int i = lo; i < hi; i++) {
        g_rowptr[i] = run;
        g_fill[i]   = run;
        run += g_deg[i];
    }
    if (t == SB_T - 1) g_rowptr[NV] = run;
}

// int2-vectorized CSR fill
__global__ void fill_kernel(const int2* __restrict__ src2,
                            const int2* __restrict__ dst2) {
    int e = blockIdx.x * blockDim.x + threadIdx.x;
    if (e < EE / 2) {
        int2 d = __ldg(&dst2[e]);
        int2 s = __ldg(&src2[e]);
        int p0 = atomicAdd(&g_fill[d.x], 1);
        g_col[p0] = s.x;
        int p1 = atomicAdd(&g_fill[d.y], 1);
        g_col[p1] = s.y;
    }
}

// ---------------- fp16 helpers ------------------------------------------------
__device__ __forceinline__ float4 u2_to_f4(uint2 u) {
    __half2 p0 = *reinterpret_cast<__half2*>(&u.x);
    __half2 p1 = *reinterpret_cast<__half2*>(&u.y);
    float2 f0 = __half22float2(p0);
    float2 f1 = __half22float2(p1);
    return make_float4(f0.x, f0.y, f1.x, f1.y);
}

__device__ __forceinline__ uint2 f4_to_u2(float4 f) {
    __half2 p0 = __float22half2_rn(make_float2(f.x, f.y));
    __half2 p1 = __float22half2_rn(make_float2(f.z, f.w));
    uint2 u;
    u.x = *reinterpret_cast<unsigned*>(&p0);
    u.y = *reinterpret_cast<unsigned*>(&p1);
    return u;
}

#define ACC4(a, u) { float4 _f = u2_to_f4(u); \
    a.x += _f.x; a.y += _f.y; a.z += _f.z; a.w += _f.w; }

// ---------------- layer-0 conv (fp32 in -> fp16 out) --------------------------
__global__ void conv_kernel(const float* __restrict__ x,
                            const float* __restrict__ w,
                            const float* __restrict__ b,
                            __half* __restrict__ hout) {
    __shared__ float s[2][TT + 8];
    int ln = threadIdx.x >> 7;
    int t  = threadIdx.x & 127;
    int n  = blockIdx.x * 2 + ln;
    s[ln][t + 4] = x[(size_t)n * TT + t];
    if (t < 4) { s[ln][t] = 0.0f; s[ln][t + TT + 4] = 0.0f; }
    __syncthreads();
    float wv[KK];
#pragma unroll
    for (int k = 0; k < KK; k++) wv[k] = __ldg(&w[k]);
    float acc = __ldg(&b[0]);
#pragma unroll
    for (int k = 0; k < KK; k++) acc += wv[k] * s[ln][t + k];
    hout[(size_t)n * TT + t] = __float2half_rn(acc);
}

// ---------------- gather helper (fp16 rows, fp32 accum) -----------------------
// Warp per node; lane owns 4 cols [4*lane, 4*lane+4) = one uint2 (8B).
// 16 independent loads in flight in the main loop (4KB/warp outstanding).
__device__ __forceinline__ float4 gather_mean_relu(int node, int lane,
                                                   const uint2* __restrict__ h2) {
    float4 a0 = u2_to_f4(__ldg(&h2[(size_t)node * 32 + lane]));  // self loop
    float4 a1 = make_float4(0.f, 0.f, 0.f, 0.f);
    float4 a2 = make_float4(0.f, 0.f, 0.f, 0.f);
    float4 a3 = make_float4(0.f, 0.f, 0.f, 0.f);
    int beg = g_rowptr[node];
    int end = g_rowptr[node + 1];
    int e = beg;
    // 16 loads in flight
    for (; e + 16 <= end; e += 16) {
        int s[16];
#pragma unroll
        for (int i = 0; i < 16; i++) s[i] = __ldg(&g_col[e + i]);
        uint2 v[16];
#pragma unroll
        for (int i = 0; i < 16; i++)
            v[i] = __ldg(&h2[(size_t)s[i] * 32 + lane]);
#pragma unroll
        for (int i = 0; i < 16; i += 4) {
            ACC4(a0, v[i + 0]); ACC4(a1, v[i + 1]);
            ACC4(a2, v[i + 2]); ACC4(a3, v[i + 3]);
        }
    }
    for (; e + 8 <= end; e += 8) {
        int s[8];
#pragma unroll
        for (int i = 0; i < 8; i++) s[i] = __ldg(&g_col[e + i]);
        uint2 v[8];
#pragma unroll
        for (int i = 0; i < 8; i++)
            v[i] = __ldg(&h2[(size_t)s[i] * 32 + lane]);
        ACC4(a0, v[0]); ACC4(a1, v[1]); ACC4(a2, v[2]); ACC4(a3, v[3]);
        ACC4(a0, v[4]); ACC4(a1, v[5]); ACC4(a2, v[6]); ACC4(a3, v[7]);
    }
    for (; e + 4 <= end; e += 4) {
        int s0 = g_col[e + 0], s1 = g_col[e + 1], s2 = g_col[e + 2], s3 = g_col[e + 3];
        uint2 v0 = __ldg(&h2[(size_t)s0 * 32 + lane]);
        uint2 v1 = __ldg(&h2[(size_t)s1 * 32 + lane]);
        uint2 v2 = __ldg(&h2[(size_t)s2 * 32 + lane]);
        uint2 v3 = __ldg(&h2[(size_t)s3 * 32 + lane]);
        ACC4(a0, v0); ACC4(a1, v1); ACC4(a2, v2); ACC4(a3, v3);
    }
    for (; e < end; e++) {
        uint2 v0 = __ldg(&h2[(size_t)g_col[e] * 32 + lane]);
        ACC4(a0, v0);
    }
    a0.x += a1.x + a2.x + a3.x;
    a0.y += a1.y + a2.y + a3.y;
    a0.z += a1.z + a2.z + a3.z;
    a0.w += a1.w + a2.w + a3.w;
    float inv = 1.0f / (float)(end - beg + 1);
    float4 r;
    r.x = fmaxf(a0.x * inv, 0.0f);
    r.y = fmaxf(a0.y * inv, 0.0f);
    r.z = fmaxf(a0.z * inv, 0.0f);
    r.w = fmaxf(a0.w * inv, 0.0f);
    return r;
}

// ---------------- fused agg(+relu) + next-layer conv -------------------------
__global__ void agg_conv_kernel(const uint2* __restrict__ hin,
                                uint2* __restrict__ hout,
                                const float* __restrict__ w,
                                const float* __restrict__ b) {
    int warp = (blockIdx.x * blockDim.x + threadIdx.x) >> 5;
    int lane = threadIdx.x & 31;
    if (warp >= NV) return;
    float4 r = gather_mean_relu(warp, lane, hin);

    const unsigned m = 0xffffffffu;
    float4 lf, rt;
    lf.x = __shfl_up_sync(m, r.x, 1);  lf.y = __shfl_up_sync(m, r.y, 1);
    lf.z = __shfl_up_sync(m, r.z, 1);  lf.w = __shfl_up_sync(m, r.w, 1);
    rt.x = __shfl_down_sync(m, r.x, 1); rt.y = __shfl_down_sync(m, r.y, 1);
    rt.z = __shfl_down_sync(m, r.z, 1); rt.w = __shfl_down_sync(m, r.w, 1);
    if (lane == 0)  lf = make_float4(0.f, 0.f, 0.f, 0.f);
    if (lane == 31) rt = make_float4(0.f, 0.f, 0.f, 0.f);

    float v[12] = { lf.x, lf.y, lf.z, lf.w,
                    r.x,  r.y,  r.z,  r.w,
                    rt.x, rt.y, rt.z, rt.w };
    float wv[KK];
#pragma unroll
    for (int k = 0; k < KK; k++) wv[k] = __ldg(&w[k]);
    float bv = __ldg(&b[0]);
    float4 o;
    o.x = bv; o.y = bv; o.z = bv; o.w = bv;
#pragma unroll
    for (int k = 0; k < KK; k++) {
        o.x += wv[k] * v[0 + k];
        o.y += wv[k] * v[1 + k];
        o.z += wv[k] * v[2 + k];
        o.w += wv[k] * v[3 + k];
    }
    hout[(size_t)warp * 32 + lane] = f4_to_u2(o);
}

// Final aggregation: relu(mean) only, into g_xh (fp16, flat for projection).
__global__ void agg_final_kernel(const uint2* __restrict__ hin) {
    int warp = (blockIdx.x * blockDim.x + threadIdx.x) >> 5;
    int lane = threadIdx.x & 31;
    if (warp >= NV) return;
    float4 r = gather_mean_relu(warp, lane, hin);
    reinterpret_cast<uint2*>(g_xh)[(size_t)warp * 32 + lane] = f4_to_u2(r);
}

// ---------------- output projection ------------------------------------------
// Blocks tile the N dimension (chunk = 256); W chunk in registers; warps
// stride over the 128 output rows; x read as fp16. y pre-initialized with bias.
#define OCHUNK 256
__global__ void out_kernel2(const float* __restrict__ Wout, float* __restrict__ y) {
    int n0 = blockIdx.x * OCHUNK;
    int C  = NV - n0; if (C > OCHUNK) C = OCHUNK;   // multiple of 8 (NV=100000)
    int w  = threadIdx.x >> 5;
    int lane = threadIdx.x & 31;

    float w0[8], w1[8], w2[8];
#pragma unroll
    for (int q = 0; q < 8; q++) {
        int idx = lane * 8 + q;
        bool val = idx < C;
        int n = n0 + idx;
        w0[q] = val ? __ldg(&Wout[0 * NV + n]) : 0.f;
        w1[q] = val ? __ldg(&Wout[1 * NV + n]) : 0.f;
        w2[q] = val ? __ldg(&Wout[2 * NV + n]) : 0.f;
    }

    for (int a = w; a < TT; a += 8) {
        const __half* xr = g_xh + (size_t)a * NV + n0;
        float p0 = 0.f, p1 = 0.f, p2 = 0.f;
#pragma unroll
        for (int q4 = 0; q4 < 2; q4++) {
            int idx = lane * 8 + q4 * 4;
            if (idx < C) {
                uint2 u = *reinterpret_cast<const uint2*>(xr + idx);
                __half2 h0 = *reinterpret_cast<__half2*>(&u.x);
                __half2 h1 = *reinterpret_cast<__half2*>(&u.y);
                float2 f0 = __half22float2(h0);
                float2 f1 = __half22float2(h1);
                int q = q4 * 4;
                p0 += f0.x * w0[q] + f0.y * w0[q + 1] + f1.x * w0[q + 2] + f1.y * w0[q + 3];
                p1 += f0.x * w1[q] + f0.y * w1[q + 1] + f1.x * w1[q + 2] + f1.y * w1[q + 3];
                p2 += f0.x * w2[q] + f0.y * w2[q + 1] + f1.x * w2[q + 2] + f1.y * w2[q + 3];
            }
        }
#pragma unroll
        for (int off = 16; off > 0; off >>= 1) {
            p0 += __shfl_down_sync(0xffffffffu, p0, off);
            p1 += __shfl_down_sync(0xffffffffu, p1, off);
            p2 += __shfl_down_sync(0xffffffffu, p2, off);
        }
        if (lane == 0) {
            atomicAdd(&y[a * 3 + 0], p0);
            atomicAdd(&y[a * 3 + 1], p1);
            atomicAdd(&y[a * 3 + 2], p2);
        }
    }
}

// ---------------- launch -----------------------------------------------------
extern "C" void kernel_launch(void* const* d_in, const int* in_sizes, int n_in,
                              void* d_out, int out_size) {
    const float* x_in    = (const float*)d_in[0];
    const int*   ei      = (const int*)d_in[1];
    const float* conv_w  = (const float*)d_in[2];   // [L,1,1,K]
    const float* conv_b  = (const float*)d_in[3];   // [L,1]
    const float* W_out   = (const float*)d_in[4];   // [3, N]
    const float* b_out   = (const float*)d_in[5];   // [3]
    float* y = (float*)d_out;                       // [T, 3]

    const int2* src2 = (const int2*)(ei);
    const int2* dst2 = (const int2*)(ei + EE);

    __half *hA, *hB;
    cudaGetSymbolAddress((void**)&hA, g_hA);
    cudaGetSymbolAddress((void**)&hB, g_hB);

    // CSR build (4 launches)
    zero_init_kernel<<<(NV + 255) / 256, 256>>>(b_out, y);
    hist_kernel<<<(EE / 2 + 255) / 256, 256>>>(dst2);
    scan_kernel<<<1, SB_T>>>();
    fill_kernel<<<(EE / 2 + 255) / 256, 256>>>(src2, dst2);

    const int agg_blocks = (NV * 32 + 255) / 256;             // 8 warps/block

    // layer 0 conv (fp32 x -> fp16 h)
    conv_kernel<<<NV / 2, 256>>>(x_in, conv_w + 0 * KK, conv_b + 0, hA);
    // agg0 + conv1 fused
    agg_conv_kernel<<<agg_blocks, 256>>>((const uint2*)hA, (uint2*)hB,
                                         conv_w + 1 * KK, conv_b + 1);
    // agg1 + conv2 fused
    agg_conv_kernel<<<agg_blocks, 256>>>((const uint2*)hB, (uint2*)hA,
                                         conv_w + 2 * KK, conv_b + 2);
    // final agg -> g_xh (fp16)
    agg_final_kernel<<<agg_blocks, 256>>>((const uint2*)hA);

    // projection
    out_kernel2<<<(NV + OCHUNK - 1) / OCHUNK, 256>>>(W_out, y);
}

// round 8
// speedup vs baseline: 1.0672x; 1.0672x over previous
#include <cuda_runtime.h>
#include <cuda_fp16.h>
#include <cstdint>

// Problem constants (fixed shapes per reference)
#define NV 100000      // vertices
#define TT 128         // temporal depth
#define EE 1600000     // edges
#define KK 9           // conv kernel
#define LL 3           // layers

// ---------------- scratch (device globals; no runtime allocation) -----------
__device__ __half g_hA[(size_t)NV * TT];   // ping  (fp16 activations)
__device__ __half g_hB[(size_t)NV * TT];   // pong
__device__ __half g_xh[(size_t)NV * TT];   // final activation (fp16, flat)
__device__ int    g_deg[NV];
__device__ int    g_fill[NV];              // fill cursor, seeded = rowptr
__device__ int    g_rowptr[NV + 1];
__device__ int    g_col[EE];

// ---------------- CSR build --------------------------------------------------
// zero degree counters AND initialize y with the output bias (independent work)
__global__ void zero_init_kernel(const float* __restrict__ bout,
                                 float* __restrict__ y) {
    int i = blockIdx.x * blockDim.x + threadIdx.x;
    if (i < NV) g_deg[i] = 0;
    if (i < TT * 3) y[i] = __ldg(&bout[i % 3]);
}

// int2-vectorized histogram over dst
__global__ void hist_kernel(const int2* __restrict__ dst2) {
    int e = blockIdx.x * blockDim.x + threadIdx.x;
    if (e < EE / 2) {
        int2 d = __ldg(&dst2[e]);
        atomicAdd(&g_deg[d.x], 1);
        atomicAdd(&g_deg[d.y], 1);
    }
}

// Single-block exclusive scan of g_deg -> g_rowptr (and seed g_fill = rowptr).
#define SB_T 1024
#define SB_CH ((NV + SB_T - 1) / SB_T)   // 98
__global__ void scan_kernel() {
    __shared__ int s[SB_T];
    int t = threadIdx.x;
    int lo = t * SB_CH;
    int hi = lo + SB_CH; if (hi > NV) hi = NV;
    int sum = 0;
    for (int i = lo; i < hi; i++) sum += g_deg[i];
    s[t] = sum;
    __syncthreads();
    for (int off = 1; off < SB_T; off <<= 1) {
        int v = (t >= off) ? s[t - off] : 0;
        __syncthreads();
        s[t] += v;
        __syncthreads();
    }
    int run = s[t] - sum;   // exclusive prefix of this thread's chunk
    for (int i = lo; i < hi; i++) {
        g_rowptr[i] = run;
        g_fill[i]   = run;
        run += g_deg[i];
    }
    if (t == SB_T - 1) g_rowptr[NV] = run;
}

// int2-vectorized CSR fill
__global__ void fill_kernel(const int2* __restrict__ src2,
                            const int2* __restrict__ dst2) {
    int e = blockIdx.x * blockDim.x + threadIdx.x;
    if (e < EE / 2) {
        int2 d = __ldg(&dst2[e]);
        int2 s = __ldg(&src2[e]);
        int p0 = atomicAdd(&g_fill[d.x], 1);
        g_col[p0] = s.x;
        int p1 = atomicAdd(&g_fill[d.y], 1);
        g_col[p1] = s.y;
    }
}

// ---------------- fp16 helpers ------------------------------------------------
__device__ __forceinline__ float4 u2_to_f4(uint2 u) {
    __half2 p0 = *reinterpret_cast<__half2*>(&u.x);
    __half2 p1 = *reinterpret_cast<__half2*>(&u.y);
    float2 f0 = __half22float2(p0);
    float2 f1 = __half22float2(p1);
    return make_float4(f0.x, f0.y, f1.x, f1.y);
}

__device__ __forceinline__ uint2 f4_to_u2(float4 f) {
    __half2 p0 = __float22half2_rn(make_float2(f.x, f.y));
    __half2 p1 = __float22half2_rn(make_float2(f.z, f.w));
    uint2 u;
    u.x = *reinterpret_cast<unsigned*>(&p0);
    u.y = *reinterpret_cast<unsigned*>(&p1);
    return u;
}

#define ACC4(a, u) { float4 _f = u2_to_f4(u); \
    a.x += _f.x; a.y += _f.y; a.z += _f.z; a.w += _f.w; }

// ---------------- layer-0 conv (fp32 in -> fp16 out) --------------------------
__global__ void conv_kernel(const float* __restrict__ x,
                            const float* __restrict__ w,
                            const float* __restrict__ b,
                            __half* __restrict__ hout) {
    __shared__ float s[2][TT + 8];
    int ln = threadIdx.x >> 7;
    int t  = threadIdx.x & 127;
    int n  = blockIdx.x * 2 + ln;
    s[ln][t + 4] = x[(size_t)n * TT + t];
    if (t < 4) { s[ln][t] = 0.0f; s[ln][t + TT + 4] = 0.0f; }
    __syncthreads();
    float wv[KK];
#pragma unroll
    for (int k = 0; k < KK; k++) wv[k] = __ldg(&w[k]);
    float acc = __ldg(&b[0]);
#pragma unroll
    for (int k = 0; k < KK; k++) acc += wv[k] * s[ln][t + k];
    hout[(size_t)n * TT + t] = __float2half_rn(acc);
}

// ---------------- gather helper (fp16 rows, fp32 accum) -----------------------
// EXACT R3 structure (proven 293us): warp per node, lane owns one uint2 (8B),
// max 8 loads in flight, no index-register arrays beyond the unroll width.
__device__ __forceinline__ float4 gather_mean_relu(int node, int lane,
                                                   const uint2* __restrict__ h2) {
    float4 a0 = u2_to_f4(__ldg(&h2[(size_t)node * 32 + lane]));  // self loop
    float4 a1 = make_float4(0.f, 0.f, 0.f, 0.f);
    float4 a2 = make_float4(0.f, 0.f, 0.f, 0.f);
    float4 a3 = make_float4(0.f, 0.f, 0.f, 0.f);
    int beg = g_rowptr[node];
    int end = g_rowptr[node + 1];
    int e = beg;
    // 8 loads in flight per iteration
    for (; e + 8 <= end; e += 8) {
        int s0 = g_col[e + 0], s1 = g_col[e + 1], s2 = g_col[e + 2], s3 = g_col[e + 3];
        int s4 = g_col[e + 4], s5 = g_col[e + 5], s6 = g_col[e + 6], s7 = g_col[e + 7];
        uint2 v0 = __ldg(&h2[(size_t)s0 * 32 + lane]);
        uint2 v1 = __ldg(&h2[(size_t)s1 * 32 + lane]);
        uint2 v2 = __ldg(&h2[(size_t)s2 * 32 + lane]);
        uint2 v3 = __ldg(&h2[(size_t)s3 * 32 + lane]);
        uint2 v4 = __ldg(&h2[(size_t)s4 * 32 + lane]);
        uint2 v5 = __ldg(&h2[(size_t)s5 * 32 + lane]);
        uint2 v6 = __ldg(&h2[(size_t)s6 * 32 + lane]);
        uint2 v7 = __ldg(&h2[(size_t)s7 * 32 + lane]);
        ACC4(a0, v0); ACC4(a1, v1); ACC4(a2, v2); ACC4(a3, v3);
        ACC4(a0, v4); ACC4(a1, v5); ACC4(a2, v6); ACC4(a3, v7);
    }
    for (; e + 4 <= end; e += 4) {
        int s0 = g_col[e + 0], s1 = g_col[e + 1], s2 = g_col[e + 2], s3 = g_col[e + 3];
        uint2 v0 = __ldg(&h2[(size_t)s0 * 32 + lane]);
        uint2 v1 = __ldg(&h2[(size_t)s1 * 32 + lane]);
        uint2 v2 = __ldg(&h2[(size_t)s2 * 32 + lane]);
        uint2 v3 = __ldg(&h2[(size_t)s3 * 32 + lane]);
        ACC4(a0, v0); ACC4(a1, v1); ACC4(a2, v2); ACC4(a3, v3);
    }
    for (; e < end; e++) {
        uint2 v0 = __ldg(&h2[(size_t)g_col[e] * 32 + lane]);
        ACC4(a0, v0);
    }
    a0.x += a1.x + a2.x + a3.x;
    a0.y += a1.y + a2.y + a3.y;
    a0.z += a1.z + a2.z + a3.z;
    a0.w += a1.w + a2.w + a3.w;
    float inv = 1.0f / (float)(end - beg + 1);
    float4 r;
    r.x = fmaxf(a0.x * inv, 0.0f);
    r.y = fmaxf(a0.y * inv, 0.0f);
    r.z = fmaxf(a0.z * inv, 0.0f);
    r.w = fmaxf(a0.w * inv, 0.0f);
    return r;
}

// ---------------- fused agg(+relu) + next-layer conv -------------------------
__global__ void __launch_bounds__(256) agg_conv_kernel(
        const uint2* __restrict__ hin,
        uint2* __restrict__ hout,
        const float* __restrict__ w,
        const float* __restrict__ b) {
    int warp = (blockIdx.x * blockDim.x + threadIdx.x) >> 5;
    int lane = threadIdx.x & 31;
    if (warp >= NV) return;
    float4 r = gather_mean_relu(warp, lane, hin);

    const unsigned m = 0xffffffffu;
    float4 lf, rt;
    lf.x = __shfl_up_sync(m, r.x, 1);  lf.y = __shfl_up_sync(m, r.y, 1);
    lf.z = __shfl_up_sync(m, r.z, 1);  lf.w = __shfl_up_sync(m, r.w, 1);
    rt.x = __shfl_down_sync(m, r.x, 1); rt.y = __shfl_down_sync(m, r.y, 1);
    rt.z = __shfl_down_sync(m, r.z, 1); rt.w = __shfl_down_sync(m, r.w, 1);
    if (lane == 0)  lf = make_float4(0.f, 0.f, 0.f, 0.f);
    if (lane == 31) rt = make_float4(0.f, 0.f, 0.f, 0.f);

    float v[12] = { lf.x, lf.y, lf.z, lf.w,
                    r.x,  r.y,  r.z,  r.w,
                    rt.x, rt.y, rt.z, rt.w };
    float wv[KK];
#pragma unroll
    for (int k = 0; k < KK; k++) wv[k] = __ldg(&w[k]);
    float bv = __ldg(&b[0]);
    float4 o;
    o.x = bv; o.y = bv; o.z = bv; o.w = bv;
#pragma unroll
    for (int k = 0; k < KK; k++) {
        o.x += wv[k] * v[0 + k];
        o.y += wv[k] * v[1 + k];
        o.z += wv[k] * v[2 + k];
        o.w += wv[k] * v[3 + k];
    }
    hout[(size_t)warp * 32 + lane] = f4_to_u2(o);
}

// Final aggregation: relu(mean) only, into g_xh (fp16, flat for projection).
__global__ void __launch_bounds__(256) agg_final_kernel(const uint2* __restrict__ hin) {
    int warp = (blockIdx.x * blockDim.x + threadIdx.x) >> 5;
    int lane = threadIdx.x & 31;
    if (warp >= NV) return;
    float4 r = gather_mean_relu(warp, lane, hin);
    reinterpret_cast<uint2*>(g_xh)[(size_t)warp * 32 + lane] = f4_to_u2(r);
}

// ---------------- output projection ------------------------------------------
// Blocks tile the N dimension (chunk = 256); W chunk in registers; warps
// stride over the 128 output rows; x read as fp16. y pre-initialized with bias.
#define OCHUNK 256
__global__ void out_kernel2(const float* __restrict__ Wout, float* __restrict__ y) {
    int n0 = blockIdx.x * OCHUNK;
    int C  = NV - n0; if (C > OCHUNK) C = OCHUNK;   // multiple of 8 (NV=100000)
    int w  = threadIdx.x >> 5;
    int lane = threadIdx.x & 31;

    float w0[8], w1[8], w2[8];
#pragma unroll
    for (int q = 0; q < 8; q++) {
        int idx = lane * 8 + q;
        bool val = idx < C;
        int n = n0 + idx;
        w0[q] = val ? __ldg(&Wout[0 * NV + n]) : 0.f;
        w1[q] = val ? __ldg(&Wout[1 * NV + n]) : 0.f;
        w2[q] = val ? __ldg(&Wout[2 * NV + n]) : 0.f;
    }

    for (int a = w; a < TT; a += 8) {
        const __half* xr = g_xh + (size_t)a * NV + n0;
        float p0 = 0.f, p1 = 0.f, p2 = 0.f;
#pragma unroll
        for (int q4 = 0; q4 < 2; q4++) {
            int idx = lane * 8 + q4 * 4;
            if (idx < C) {
                uint2 u = *reinterpret_cast<const uint2*>(xr + idx);
                __half2 h0 = *reinterpret_cast<__half2*>(&u.x);
                __half2 h1 = *reinterpret_cast<__half2*>(&u.y);
                float2 f0 = __half22float2(h0);
                float2 f1 = __half22float2(h1);
                int q = q4 * 4;
                p0 += f0.x * w0[q] + f0.y * w0[q + 1] + f1.x * w0[q + 2] + f1.y * w0[q + 3];
                p1 += f0.x * w1[q] + f0.y * w1[q + 1] + f1.x * w1[q + 2] + f1.y * w1[q + 3];
                p2 += f0.x * w2[q] + f0.y * w2[q + 1] + f1.x * w2[q + 2] + f1.y * w2[q + 3];
            }
        }
#pragma unroll
        for (int off = 16; off > 0; off >>= 1) {
            p0 += __shfl_down_sync(0xffffffffu, p0, off);
            p1 += __shfl_down_sync(0xffffffffu, p1, off);
            p2 += __shfl_down_sync(0xffffffffu, p2, off);
        }
        if (lane == 0) {
            atomicAdd(&y[a * 3 + 0], p0);
            atomicAdd(&y[a * 3 + 1], p1);
            atomicAdd(&y[a * 3 + 2], p2);
        }
    }
}

// ---------------- launch -----------------------------------------------------
extern "C" void kernel_launch(void* const* d_in, const int* in_sizes, int n_in,
                              void* d_out, int out_size) {
    const float* x_in    = (const float*)d_in[0];
    const int*   ei      = (const int*)d_in[1];
    const float* conv_w  = (const float*)d_in[2];   // [L,1,1,K]
    const float* conv_b  = (const float*)d_in[3];   // [L,1]
    const float* W_out   = (const float*)d_in[4];   // [3, N]
    const float* b_out   = (const float*)d_in[5];   // [3]
    float* y = (float*)d_out;                       // [T, 3]

    const int2* src2 = (const int2*)(ei);
    const int2* dst2 = (const int2*)(ei + EE);

    __half *hA, *hB;
    cudaGetSymbolAddress((void**)&hA, g_hA);
    cudaGetSymbolAddress((void**)&hB, g_hB);

    // CSR build (4 launches)
    zero_init_kernel<<<(NV + 255) / 256, 256>>>(b_out, y);
    hist_kernel<<<(EE / 2 + 255) / 256, 256>>>(dst2);
    scan_kernel<<<1, SB_T>>>();
    fill_kernel<<<(EE / 2 + 255) / 256, 256>>>(src2, dst2);

    const int agg_blocks = (NV * 32 + 255) / 256;             // 8 warps/block

    // layer 0 conv (fp32 x -> fp16 h)
    conv_kernel<<<NV / 2, 256>>>(x_in, conv_w + 0 * KK, conv_b + 0, hA);
    // agg0 + conv1 fused
    agg_conv_kernel<<<agg_blocks, 256>>>((const uint2*)hA, (uint2*)hB,
                                         conv_w + 1 * KK, conv_b + 1);
    // agg1 + conv2 fused
    agg_conv_kernel<<<agg_blocks, 256>>>((const uint2*)hB, (uint2*)hA,
                                         conv_w + 2 * KK, conv_b + 2);
    // final agg -> g_xh (fp16)
    agg_final_kernel<<<agg_blocks, 256>>>((const uint2*)hA);

    // projection
    out_kernel2<<<(NV + OCHUNK - 1) / OCHUNK, 256>>>(W_out, y);
}

// round 11
// speedup vs baseline: 1.5315x; 1.4350x over previous
#include <cuda_runtime.h>
#include <cuda_fp16.h>
#include <cstdint>

// Problem constants (fixed shapes per reference)
#define NV 100000      // vertices
#define TT 128         // temporal depth
#define EE 1600000     // edges
#define KK 9           // conv kernel
#define LL 3           // layers

// ---------------- scratch (device globals; no runtime allocation) -----------
__device__ __half g_hA[(size_t)NV * TT];   // ping  (fp16 activations)
__device__ __half g_hB[(size_t)NV * TT];   // pong
__device__ __half g_xh[(size_t)NV * TT];   // final activation (fp16, flat)
__device__ int    g_deg[NV];
__device__ int    g_fill[NV];              // fill cursor, seeded = rowptr
__device__ int    g_rowptr[NV + 1];
__device__ int    g_col[EE];
__device__ int    g_blocksum[256];
__device__ int    g_blockoff[256];

// ---------------- CSR build --------------------------------------------------
// zero degree counters AND initialize y with the output bias (independent work)
__global__ void zero_init_kernel(const float* __restrict__ bout,
                                 float* __restrict__ y) {
    int i = blockIdx.x * blockDim.x + threadIdx.x;
    if (i < NV) g_deg[i] = 0;
    if (i < TT * 3) y[i] = __ldg(&bout[i % 3]);
}

// int2-vectorized histogram over dst
__global__ void hist_kernel(const int2* __restrict__ dst2) {
    int e = blockIdx.x * blockDim.x + threadIdx.x;
    if (e < EE / 2) {
        int2 d = __ldg(&dst2[e]);
        atomicAdd(&g_deg[d.x], 1);
        atomicAdd(&g_deg[d.y], 1);
    }
}

// Multi-block coalesced scan (proven R3 structure):
// per-block reduce -> parallel scan of block sums -> per-block scan + add offset.
#define SCAN_B 512
__global__ void scan_partial_kernel() {
    __shared__ int s[SCAN_B];
    int i = blockIdx.x * SCAN_B + threadIdx.x;
    int v = (i < NV) ? g_deg[i] : 0;
    s[threadIdx.x] = v;
    __syncthreads();
    for (int off = SCAN_B / 2; off > 0; off >>= 1) {
        if (threadIdx.x < off) s[threadIdx.x] += s[threadIdx.x + off];
        __syncthreads();
    }
    if (threadIdx.x == 0) g_blocksum[blockIdx.x] = s[0];
}

__global__ void scan_tops_kernel(int nblocks) {
    __shared__ int s[256];
    int v = (threadIdx.x < nblocks) ? g_blocksum[threadIdx.x] : 0;
    s[threadIdx.x] = v;
    __syncthreads();
    for (int off = 1; off < 256; off <<= 1) {
        int t = (threadIdx.x >= off) ? s[threadIdx.x - off] : 0;
        __syncthreads();
        s[threadIdx.x] += t;
        __syncthreads();
    }
    if (threadIdx.x < nblocks) g_blockoff[threadIdx.x] = s[threadIdx.x] - v;
}

// also seeds g_fill = rowptr (coalesced), so fill needs one atomicAdd only
__global__ void scan_final_kernel() {
    __shared__ int s[SCAN_B];
    int i = blockIdx.x * SCAN_B + threadIdx.x;
    int v = (i < NV) ? g_deg[i] : 0;
    s[threadIdx.x] = v;
    __syncthreads();
    for (int off = 1; off < SCAN_B; off <<= 1) {
        int t = (threadIdx.x >= off) ? s[threadIdx.x - off] : 0;
        __syncthreads();
        s[threadIdx.x] += t;
        __syncthreads();
    }
    int excl = g_blockoff[blockIdx.x] + s[threadIdx.x] - v;
    if (i <= NV) g_rowptr[i] = excl;
    if (i < NV)  g_fill[i]   = excl;
}

// int2-vectorized CSR fill (direct atomicAdd on rowptr-seeded cursor)
__global__ void fill_kernel(const int2* __restrict__ src2,
                            const int2* __restrict__ dst2) {
    int e = blockIdx.x * blockDim.x + threadIdx.x;
    if (e < EE / 2) {
        int2 d = __ldg(&dst2[e]);
        int2 s = __ldg(&src2[e]);
        int p0 = atomicAdd(&g_fill[d.x], 1);
        g_col[p0] = s.x;
        int p1 = atomicAdd(&g_fill[d.y], 1);
        g_col[p1] = s.y;
    }
}

// ---------------- fp16 helpers ------------------------------------------------
__device__ __forceinline__ float4 u2_to_f4(uint2 u) {
    __half2 p0 = *reinterpret_cast<__half2*>(&u.x);
    __half2 p1 = *reinterpret_cast<__half2*>(&u.y);
    float2 f0 = __half22float2(p0);
    float2 f1 = __half22float2(p1);
    return make_float4(f0.x, f0.y, f1.x, f1.y);
}

__device__ __forceinline__ uint2 f4_to_u2(float4 f) {
    __half2 p0 = __float22half2_rn(make_float2(f.x, f.y));
    __half2 p1 = __float22half2_rn(make_float2(f.z, f.w));
    uint2 u;
    u.x = *reinterpret_cast<unsigned*>(&p0);
    u.y = *reinterpret_cast<unsigned*>(&p1);
    return u;
}

#define ACC4(a, u) { float4 _f = u2_to_f4(u); \
    a.x += _f.x; a.y += _f.y; a.z += _f.z; a.w += _f.w; }

// ---------------- layer-0 conv (fp32 in -> fp16 out) --------------------------
__global__ void conv_kernel(const float* __restrict__ x,
                            const float* __restrict__ w,
                            const float* __restrict__ b,
                            __half* __restrict__ hout) {
    __shared__ float s[2][TT + 8];
    int ln = threadIdx.x >> 7;
    int t  = threadIdx.x & 127;
    int n  = blockIdx.x * 2 + ln;
    s[ln][t + 4] = x[(size_t)n * TT + t];
    if (t < 4) { s[ln][t] = 0.0f; s[ln][t + TT + 4] = 0.0f; }
    __syncthreads();
    float wv[KK];
#pragma unroll
    for (int k = 0; k < KK; k++) wv[k] = __ldg(&w[k]);
    float acc = __ldg(&b[0]);
#pragma unroll
    for (int k = 0; k < KK; k++) acc += wv[k] * s[ln][t + k];
    hout[(size_t)n * TT + t] = __float2half_rn(acc);
}

// ---------------- gather helper (fp16 rows, fp32 accum) -----------------------
// Proven R3 structure: warp per node, lane owns one uint2 (8B), 8 loads in flight.
__device__ __forceinline__ float4 gather_mean_relu(int node, int lane,
                                                   const uint2* __restrict__ h2) {
    float4 a0 = u2_to_f4(__ldg(&h2[(size_t)node * 32 + lane]));  // self loop
    float4 a1 = make_float4(0.f, 0.f, 0.f, 0.f);
    float4 a2 = make_float4(0.f, 0.f, 0.f, 0.f);
    float4 a3 = make_float4(0.f, 0.f, 0.f, 0.f);
    int beg = g_rowptr[node];
    int end = g_rowptr[node + 1];
    int e = beg;
    for (; e + 8 <= end; e += 8) {
        int s0 = g_col[e + 0], s1 = g_col[e + 1], s2 = g_col[e + 2], s3 = g_col[e + 3];
        int s4 = g_col[e + 4], s5 = g_col[e + 5], s6 = g_col[e + 6], s7 = g_col[e + 7];
        uint2 v0 = __ldg(&h2[(size_t)s0 * 32 + lane]);
        uint2 v1 = __ldg(&h2[(size_t)s1 * 32 + lane]);
        uint2 v2 = __ldg(&h2[(size_t)s2 * 32 + lane]);
        uint2 v3 = __ldg(&h2[(size_t)s3 * 32 + lane]);
        uint2 v4 = __ldg(&h2[(size_t)s4 * 32 + lane]);
        uint2 v5 = __ldg(&h2[(size_t)s5 * 32 + lane]);
        uint2 v6 = __ldg(&h2[(size_t)s6 * 32 + lane]);
        uint2 v7 = __ldg(&h2[(size_t)s7 * 32 + lane]);
        ACC4(a0, v0); ACC4(a1, v1); ACC4(a2, v2); ACC4(a3, v3);
        ACC4(a0, v4); ACC4(a1, v5); ACC4(a2, v6); ACC4(a3, v7);
    }
    for (; e + 4 <= end; e += 4) {
        int s0 = g_col[e + 0], s1 = g_col[e + 1], s2 = g_col[e + 2], s3 = g_col[e + 3];
        uint2 v0 = __ldg(&h2[(size_t)s0 * 32 + lane]);
        uint2 v1 = __ldg(&h2[(size_t)s1 * 32 + lane]);
        uint2 v2 = __ldg(&h2[(size_t)s2 * 32 + lane]);
        uint2 v3 = __ldg(&h2[(size_t)s3 * 32 + lane]);
        ACC4(a0, v0); ACC4(a1, v1); ACC4(a2, v2); ACC4(a3, v3);
    }
    for (; e < end; e++) {
        uint2 v0 = __ldg(&h2[(size_t)g_col[e] * 32 + lane]);
        ACC4(a0, v0);
    }
    a0.x += a1.x + a2.x + a3.x;
    a0.y += a1.y + a2.y + a3.y;
    a0.z += a1.z + a2.z + a3.z;
    a0.w += a1.w + a2.w + a3.w;
    float inv = 1.0f / (float)(end - beg + 1);
    float4 r;
    r.x = fmaxf(a0.x * inv, 0.0f);
    r.y = fmaxf(a0.y * inv, 0.0f);
    r.z = fmaxf(a0.z * inv, 0.0f);
    r.w = fmaxf(a0.w * inv, 0.0f);
    return r;
}

// ---------------- fused agg(+relu) + next-layer conv -------------------------
__global__ void agg_conv_kernel(const uint2* __restrict__ hin,
                                uint2* __restrict__ hout,
                                const float* __restrict__ w,
                                const float* __restrict__ b) {
    int warp = (blockIdx.x * blockDim.x + threadIdx.x) >> 5;
    int lane = threadIdx.x & 31;
    if (warp >= NV) return;
    float4 r = gather_mean_relu(warp, lane, hin);

    const unsigned m = 0xffffffffu;
    float4 lf, rt;
    lf.x = __shfl_up_sync(m, r.x, 1);  lf.y = __shfl_up_sync(m, r.y, 1);
    lf.z = __shfl_up_sync(m, r.z, 1);  lf.w = __shfl_up_sync(m, r.w, 1);
    rt.x = __shfl_down_sync(m, r.x, 1); rt.y = __shfl_down_sync(m, r.y, 1);
    rt.z = __shfl_down_sync(m, r.z, 1); rt.w = __shfl_down_sync(m, r.w, 1);
    if (lane == 0)  lf = make_float4(0.f, 0.f, 0.f, 0.f);
    if (lane == 31) rt = make_float4(0.f, 0.f, 0.f, 0.f);

    float v[12] = { lf.x, lf.y, lf.z, lf.w,
                    r.x,  r.y,  r.z,  r.w,
                    rt.x, rt.y, rt.z, rt.w };
    float wv[KK];
#pragma unroll
    for (int k = 0; k < KK; k++) wv[k] = __ldg(&w[k]);
    float bv = __ldg(&b[0]);
    float4 o;
    o.x = bv; o.y = bv; o.z = bv; o.w = bv;
#pragma unroll
    for (int k = 0; k < KK; k++) {
        o.x += wv[k] * v[0 + k];
        o.y += wv[k] * v[1 + k];
        o.z += wv[k] * v[2 + k];
        o.w += wv[k] * v[3 + k];
    }
    hout[(size_t)warp * 32 + lane] = f4_to_u2(o);
}

// Final aggregation: relu(mean) only, into g_xh (fp16, flat for projection).
__global__ void agg_final_kernel(const uint2* __restrict__ hin) {
    int warp = (blockIdx.x * blockDim.x + threadIdx.x) >> 5;
    int lane = threadIdx.x & 31;
    if (warp >= NV) return;
    float4 r = gather_mean_relu(warp, lane, hin);
    reinterpret_cast<uint2*>(g_xh)[(size_t)warp * 32 + lane] = f4_to_u2(r);
}

// ---------------- output projection ------------------------------------------
#define OCHUNK 256
__global__ void out_kernel2(const float* __restrict__ Wout, float* __restrict__ y) {
    int n0 = blockIdx.x * OCHUNK;
    int C  = NV - n0; if (C > OCHUNK) C = OCHUNK;   // multiple of 8 (NV=100000)
    int w  = threadIdx.x >> 5;
    int lane = threadIdx.x & 31;

    float w0[8], w1[8], w2[8];
#pragma unroll
    for (int q = 0; q < 8; q++) {
        int idx = lane * 8 + q;
        bool val = idx < C;
        int n = n0 + idx;
        w0[q] = val ? __ldg(&Wout[0 * NV + n]) : 0.f;
        w1[q] = val ? __ldg(&Wout[1 * NV + n]) : 0.f;
        w2[q] = val ? __ldg(&Wout[2 * NV + n]) : 0.f;
    }

    for (int a = w; a < TT; a += 8) {
        const __half* xr = g_xh + (size_t)a * NV + n0;
        float p0 = 0.f, p1 = 0.f, p2 = 0.f;
#pragma unroll
        for (int q4 = 0; q4 < 2; q4++) {
            int idx = lane * 8 + q4 * 4;
            if (idx < C) {
                uint2 u = *reinterpret_cast<const uint2*>(xr + idx);
                __half2 h0 = *reinterpret_cast<__half2*>(&u.x);
                __half2 h1 = *reinterpret_cast<__half2*>(&u.y);
                float2 f0 = __half22float2(h0);
                float2 f1 = __half22float2(h1);
                int q = q4 * 4;
                p0 += f0.x * w0[q] + f0.y * w0[q + 1] + f1.x * w0[q + 2] + f1.y * w0[q + 3];
                p1 += f0.x * w1[q] + f0.y * w1[q + 1] + f1.x * w1[q + 2] + f1.y * w1[q + 3];
                p2 += f0.x * w2[q] + f0.y * w2[q + 1] + f1.x * w2[q + 2] + f1.y * w2[q + 3];
            }
        }
#pragma unroll
        for (int off = 16; off > 0; off >>= 1) {
            p0 += __shfl_down_sync(0xffffffffu, p0, off);
            p1 += __shfl_down_sync(0xffffffffu, p1, off);
            p2 += __shfl_down_sync(0xffffffffu, p2, off);
        }
        if (lane == 0) {
            atomicAdd(&y[a * 3 + 0], p0);
            atomicAdd(&y[a * 3 + 1], p1);
            atomicAdd(&y[a * 3 + 2], p2);
        }
    }
}

// ---------------- launch -----------------------------------------------------
extern "C" void kernel_launch(void* const* d_in, const int* in_sizes, int n_in,
                              void* d_out, int out_size) {
    const float* x_in    = (const float*)d_in[0];
    const int*   ei      = (const int*)d_in[1];
    const float* conv_w  = (const float*)d_in[2];   // [L,1,1,K]
    const float* conv_b  = (const float*)d_in[3];   // [L,1]
    const float* W_out   = (const float*)d_in[4];   // [3, N]
    const float* b_out   = (const float*)d_in[5];   // [3]
    float* y = (float*)d_out;                       // [T, 3]

    const int2* src2 = (const int2*)(ei);
    const int2* dst2 = (const int2*)(ei + EE);

    __half *hA, *hB;
    cudaGetSymbolAddress((void**)&hA, g_hA);
    cudaGetSymbolAddress((void**)&hB, g_hB);

    const int scan_blocks = (NV + 1 + SCAN_B - 1) / SCAN_B;   // 196

    // CSR build (multi-block coalesced scan — proven fast)
    zero_init_kernel<<<(NV + 255) / 256, 256>>>(b_out, y);
    hist_kernel<<<(EE / 2 + 255) / 256, 256>>>(dst2);
    scan_partial_kernel<<<scan_blocks, SCAN_B>>>();
    scan_tops_kernel<<<1, 256>>>(scan_blocks);
    scan_final_kernel<<<scan_blocks, SCAN_B>>>();
    fill_kernel<<<(EE / 2 + 255) / 256, 256>>>(src2, dst2);

    const int agg_blocks = (NV * 32 + 255) / 256;             // 8 warps/block

    // layer 0 conv (fp32 x -> fp16 h)
    conv_kernel<<<NV / 2, 256>>>(x_in, conv_w + 0 * KK, conv_b + 0, hA);
    // agg0 + conv1 fused
    agg_conv_kernel<<<agg_blocks, 256>>>((const uint2*)hA, (uint2*)hB,
                                         conv_w + 1 * KK, conv_b + 1);
    // agg1 + conv2 fused
    agg_conv_kernel<<<agg_blocks, 256>>>((const uint2*)hB, (uint2*)hA,
                                         conv_w + 2 * KK, conv_b + 2);
    // final agg -> g_xh (fp16)
    agg_final_kernel<<<agg_blocks, 256>>>((const uint2*)hA);

    // projection
    out_kernel2<<<(NV + OCHUNK - 1) / OCHUNK, 256>>>(W_out, y);
}

// round 14
// speedup vs baseline: 1.8513x; 1.2088x over previous
#include <cuda_runtime.h>
#include <cuda_fp16.h>
#include <cstdint>

// Problem constants (fixed shapes per reference)
#define NV 100000      // vertices
#define TT 128         // temporal depth
#define EE 1600000     // edges
#define KK 9           // conv kernel
#define LL 3           // layers

// ---------------- scratch (device globals; no runtime allocation) -----------
__device__ __half g_hA[(size_t)NV * TT];   // ping  (fp16 activations)
__device__ __half g_hB[(size_t)NV * TT];   // pong
__device__ __half g_xh[(size_t)NV * TT];   // final activation (fp16, flat)
__device__ int    g_deg[NV];
__device__ int    g_fill[NV];              // fill cursor, seeded = rowptr
__device__ int    g_rowptr[NV + 1];
__device__ int    g_col[EE];
__device__ int    g_blocksum[256];
__device__ int    g_blockoff[256];

// ---------------- CSR build --------------------------------------------------
__global__ void zero_init_kernel(const float* __restrict__ bout,
                                 float* __restrict__ y) {
    int i = blockIdx.x * blockDim.x + threadIdx.x;
    if (i < NV) g_deg[i] = 0;
    if (i < TT * 3) y[i] = __ldg(&bout[i % 3]);
}

__global__ void hist_kernel(const int2* __restrict__ dst2) {
    int e = blockIdx.x * blockDim.x + threadIdx.x;
    if (e < EE / 2) {
        int2 d = __ldg(&dst2[e]);
        atomicAdd(&g_deg[d.x], 1);
        atomicAdd(&g_deg[d.y], 1);
    }
}

#define SCAN_B 512
__global__ void scan_partial_kernel() {
    __shared__ int s[SCAN_B];
    int i = blockIdx.x * SCAN_B + threadIdx.x;
    int v = (i < NV) ? g_deg[i] : 0;
    s[threadIdx.x] = v;
    __syncthreads();
    for (int off = SCAN_B / 2; off > 0; off >>= 1) {
        if (threadIdx.x < off) s[threadIdx.x] += s[threadIdx.x + off];
        __syncthreads();
    }
    if (threadIdx.x == 0) g_blocksum[blockIdx.x] = s[0];
}

__global__ void scan_tops_kernel(int nblocks) {
    __shared__ int s[256];
    int v = (threadIdx.x < nblocks) ? g_blocksum[threadIdx.x] : 0;
    s[threadIdx.x] = v;
    __syncthreads();
    for (int off = 1; off < 256; off <<= 1) {
        int t = (threadIdx.x >= off) ? s[threadIdx.x - off] : 0;
        __syncthreads();
        s[threadIdx.x] += t;
        __syncthreads();
    }
    if (threadIdx.x < nblocks) g_blockoff[threadIdx.x] = s[threadIdx.x] - v;
}

__global__ void scan_final_kernel() {
    __shared__ int s[SCAN_B];
    int i = blockIdx.x * SCAN_B + threadIdx.x;
    int v = (i < NV) ? g_deg[i] : 0;
    s[threadIdx.x] = v;
    __syncthreads();
    for (int off = 1; off < SCAN_B; off <<= 1) {
        int t = (threadIdx.x >= off) ? s[threadIdx.x - off] : 0;
        __syncthreads();
        s[threadIdx.x] += t;
        __syncthreads();
    }
    int excl = g_blockoff[blockIdx.x] + s[threadIdx.x] - v;
    if (i <= NV) g_rowptr[i] = excl;
    if (i < NV)  g_fill[i]   = excl;
}

__global__ void fill_kernel(const int2* __restrict__ src2,
                            const int2* __restrict__ dst2) {
    int e = blockIdx.x * blockDim.x + threadIdx.x;
    if (e < EE / 2) {
        int2 d = __ldg(&dst2[e]);
        int2 s = __ldg(&src2[e]);
        int p0 = atomicAdd(&g_fill[d.x], 1);
        g_col[p0] = s.x;
        int p1 = atomicAdd(&g_fill[d.y], 1);
        g_col[p1] = s.y;
    }
}

// ---------------- fp16 helpers ------------------------------------------------
__device__ __forceinline__ __half2 u2lo(uint2 u) { return *reinterpret_cast<__half2*>(&u.x); }
__device__ __forceinline__ __half2 u2hi(uint2 u) { return *reinterpret_cast<__half2*>(&u.y); }

__device__ __forceinline__ float4 u2_to_f4(uint2 u) {
    float2 f0 = __half22float2(u2lo(u));
    float2 f1 = __half22float2(u2hi(u));
    return make_float4(f0.x, f0.y, f1.x, f1.y);
}

__device__ __forceinline__ uint2 f4_to_u2(float4 f) {
    __half2 p0 = __float22half2_rn(make_float2(f.x, f.y));
    __half2 p1 = __float22half2_rn(make_float2(f.z, f.w));
    uint2 u;
    u.x = *reinterpret_cast<unsigned*>(&p0);
    u.y = *reinterpret_cast<unsigned*>(&p1);
    return u;
}

#define ACC4(a, u) { float4 _f = u2_to_f4(u); \
    a.x += _f.x; a.y += _f.y; a.z += _f.z; a.w += _f.w; }

// accumulate a (lo,hi) half2 pair into a float4
#define ACCP(a, l, h) { float2 _f0 = __half22float2(l); float2 _f1 = __half22float2(h); \
    a.x += _f0.x; a.y += _f0.y; a.z += _f1.x; a.w += _f1.y; }

// ---------------- layer-0 conv (fp32 in -> fp16 out) --------------------------
__global__ void conv_kernel(const float* __restrict__ x,
                            const float* __restrict__ w,
                            const float* __restrict__ b,
                            __half* __restrict__ hout) {
    __shared__ float s[2][TT + 8];
    int ln = threadIdx.x >> 7;
    int t  = threadIdx.x & 127;
    int n  = blockIdx.x * 2 + ln;
    s[ln][t + 4] = x[(size_t)n * TT + t];
    if (t < 4) { s[ln][t] = 0.0f; s[ln][t + TT + 4] = 0.0f; }
    __syncthreads();
    float wv[KK];
#pragma unroll
    for (int k = 0; k < KK; k++) wv[k] = __ldg(&w[k]);
    float acc = __ldg(&b[0]);
#pragma unroll
    for (int k = 0; k < KK; k++) acc += wv[k] * s[ln][t + k];
    hout[(size_t)n * TT + t] = __float2half_rn(acc);
}

// ---------------- gather helper (fp16 rows, pairwise half2 tree) --------------
// Warp per node; lane owns one uint2 (8B = 4 cols). 8 loads in flight.
// Groups of 4 rows are pre-summed with 2 levels of HADD2 (2 fp16 roundings),
// then converted and accumulated in fp32 — ~4x fewer ALU ops in the hot loop.
__device__ __forceinline__ float4 gather_mean_relu(int node, int lane,
                                                   const uint2* __restrict__ h2) {
    float4 a0 = u2_to_f4(__ldg(&h2[(size_t)node * 32 + lane]));  // self loop (fp32)
    float4 a1 = make_float4(0.f, 0.f, 0.f, 0.f);
    int beg = g_rowptr[node];
    int end = g_rowptr[node + 1];
    int e = beg;
    for (; e + 8 <= end; e += 8) {
        int s0 = g_col[e + 0], s1 = g_col[e + 1], s2 = g_col[e + 2], s3 = g_col[e + 3];
        int s4 = g_col[e + 4], s5 = g_col[e + 5], s6 = g_col[e + 6], s7 = g_col[e + 7];
        uint2 v0 = __ldg(&h2[(size_t)s0 * 32 + lane]);
        uint2 v1 = __ldg(&h2[(size_t)s1 * 32 + lane]);
        uint2 v2 = __ldg(&h2[(size_t)s2 * 32 + lane]);
        uint2 v3 = __ldg(&h2[(size_t)s3 * 32 + lane]);
        uint2 v4 = __ldg(&h2[(size_t)s4 * 32 + lane]);
        uint2 v5 = __ldg(&h2[(size_t)s5 * 32 + lane]);
        uint2 v6 = __ldg(&h2[(size_t)s6 * 32 + lane]);
        uint2 v7 = __ldg(&h2[(size_t)s7 * 32 + lane]);
        // level 1: pairwise
        __half2 l01 = __hadd2(u2lo(v0), u2lo(v1)), h01 = __hadd2(u2hi(v0), u2hi(v1));
        __half2 l23 = __hadd2(u2lo(v2), u2lo(v3)), h23 = __hadd2(u2hi(v2), u2hi(v3));
        __half2 l45 = __hadd2(u2lo(v4), u2lo(v5)), h45 = __hadd2(u2hi(v4), u2hi(v5));
        __half2 l67 = __hadd2(u2lo(v6), u2lo(v7)), h67 = __hadd2(u2hi(v6), u2hi(v7));
        // level 2: groups of 4
        __half2 lA = __hadd2(l01, l23), hA = __hadd2(h01, h23);
        __half2 lB = __hadd2(l45, l67), hB = __hadd2(h45, h67);
        // fp32 accumulate
        ACCP(a0, lA, hA);
        ACCP(a1, lB, hB);
    }
    for (; e + 4 <= end; e += 4) {
        int s0 = g_col[e + 0], s1 = g_col[e + 1], s2 = g_col[e + 2], s3 = g_col[e + 3];
        uint2 v0 = __ldg(&h2[(size_t)s0 * 32 + lane]);
        uint2 v1 = __ldg(&h2[(size_t)s1 * 32 + lane]);
        uint2 v2 = __ldg(&h2[(size_t)s2 * 32 + lane]);
        uint2 v3 = __ldg(&h2[(size_t)s3 * 32 + lane]);
        __half2 l01 = __hadd2(u2lo(v0), u2lo(v1)), h01 = __hadd2(u2hi(v0), u2hi(v1));
        __half2 l23 = __hadd2(u2lo(v2), u2lo(v3)), h23 = __hadd2(u2hi(v2), u2hi(v3));
        ACCP(a0, l01, h01);
        ACCP(a1, l23, h23);
    }
    for (; e < end; e++) {
        uint2 v0 = __ldg(&h2[(size_t)g_col[e] * 32 + lane]);
        ACC4(a0, v0);
    }
    a0.x += a1.x; a0.y += a1.y; a0.z += a1.z; a0.w += a1.w;
    float inv = 1.0f / (float)(end - beg + 1);
    float4 r;
    r.x = fmaxf(a0.x * inv, 0.0f);
    r.y = fmaxf(a0.y * inv, 0.0f);
    r.z = fmaxf(a0.z * inv, 0.0f);
    r.w = fmaxf(a0.w * inv, 0.0f);
    return r;
}

// ---------------- fused agg(+relu) + next-layer conv -------------------------
__global__ void agg_conv_kernel(const uint2* __restrict__ hin,
                                uint2* __restrict__ hout,
                                const float* __restrict__ w,
                                const float* __restrict__ b) {
    int warp = (blockIdx.x * blockDim.x + threadIdx.x) >> 5;
    int lane = threadIdx.x & 31;
    if (warp >= NV) return;
    float4 r = gather_mean_relu(warp, lane, hin);

    const unsigned m = 0xffffffffu;
    float4 lf, rt;
    lf.x = __shfl_up_sync(m, r.x, 1);  lf.y = __shfl_up_sync(m, r.y, 1);
    lf.z = __shfl_up_sync(m, r.z, 1);  lf.w = __shfl_up_sync(m, r.w, 1);
    rt.x = __shfl_down_sync(m, r.x, 1); rt.y = __shfl_down_sync(m, r.y, 1);
    rt.z = __shfl_down_sync(m, r.z, 1); rt.w = __shfl_down_sync(m, r.w, 1);
    if (lane == 0)  lf = make_float4(0.f, 0.f, 0.f, 0.f);
    if (lane == 31) rt = make_float4(0.f, 0.f, 0.f, 0.f);

    float v[12] = { lf.x, lf.y, lf.z, lf.w,
                    r.x,  r.y,  r.z,  r.w,
                    rt.x, rt.y, rt.z, rt.w };
    float wv[KK];
#pragma unroll
    for (int k = 0; k < KK; k++) wv[k] = __ldg(&w[k]);
    float bv = __ldg(&b[0]);
    float4 o;
    o.x = bv; o.y = bv; o.z = bv; o.w = bv;
#pragma unroll
    for (int k = 0; k < KK; k++) {
        o.x += wv[k] * v[0 + k];
        o.y += wv[k] * v[1 + k];
        o.z += wv[k] * v[2 + k];
        o.w += wv[k] * v[3 + k];
    }
    hout[(size_t)warp * 32 + lane] = f4_to_u2(o);
}

// Final aggregation: relu(mean) only, into g_xh (fp16, flat for projection).
__global__ void agg_final_kernel(const uint2* __restrict__ hin) {
    int warp = (blockIdx.x * blockDim.x + threadIdx.x) >> 5;
    int lane = threadIdx.x & 31;
    if (warp >= NV) return;
    float4 r = gather_mean_relu(warp, lane, hin);
    reinterpret_cast<uint2*>(g_xh)[(size_t)warp * 32 + lane] = f4_to_u2(r);
}

// ---------------- output projection ------------------------------------------
#define OCHUNK 256
__global__ void out_kernel2(const float* __restrict__ Wout, float* __restrict__ y) {
    int n0 = blockIdx.x * OCHUNK;
    int C  = NV - n0; if (C > OCHUNK) C = OCHUNK;   // multiple of 8 (NV=100000)
    int w  = threadIdx.x >> 5;
    int lane = threadIdx.x & 31;

    float w0[8], w1[8], w2[8];
#pragma unroll
    for (int q = 0; q < 8; q++) {
        int idx = lane * 8 + q;
        bool val = idx < C;
        int n = n0 + idx;
        w0[q] = val ? __ldg(&Wout[0 * NV + n]) : 0.f;
        w1[q] = val ? __ldg(&Wout[1 * NV + n]) : 0.f;
        w2[q] = val ? __ldg(&Wout[2 * NV + n]) : 0.f;
    }

    for (int a = w; a < TT; a += 8) {
        const __half* xr = g_xh + (size_t)a * NV + n0;
        float p0 = 0.f, p1 = 0.f, p2 = 0.f;
#pragma unroll
        for (int q4 = 0; q4 < 2; q4++) {
            int idx = lane * 8 + q4 * 4;
            if (idx < C) {
                uint2 u = *reinterpret_cast<const uint2*>(xr + idx);
                float2 f0 = __half22float2(*reinterpret_cast<__half2*>(&u.x));
                float2 f1 = __half22float2(*reinterpret_cast<__half2*>(&u.y));
                int q = q4 * 4;
                p0 += f0.x * w0[q] + f0.y * w0[q + 1] + f1.x * w0[q + 2] + f1.y * w0[q + 3];
                p1 += f0.x * w1[q] + f0.y * w1[q + 1] + f1.x * w1[q + 2] + f1.y * w1[q + 3];
                p2 += f0.x * w2[q] + f0.y * w2[q + 1] + f1.x * w2[q + 2] + f1.y * w2[q + 3];
            }
        }
#pragma unroll
        for (int off = 16; off > 0; off >>= 1) {
            p0 += __shfl_down_sync(0xffffffffu, p0, off);
            p1 += __shfl_down_sync(0xffffffffu, p1, off);
            p2 += __shfl_down_sync(0xffffffffu, p2, off);
        }
        if (lane == 0) {
            atomicAdd(&y[a * 3 + 0], p0);
            atomicAdd(&y[a * 3 + 1], p1);
            atomicAdd(&y[a * 3 + 2], p2);
        }
    }
}

// ---------------- launch -----------------------------------------------------
extern "C" void kernel_launch(void* const* d_in, const int* in_sizes, int n_in,
                              void* d_out, int out_size) {
    const float* x_in    = (const float*)d_in[0];
    const int*   ei      = (const int*)d_in[1];
    const float* conv_w  = (const float*)d_in[2];   // [L,1,1,K]
    const float* conv_b  = (const float*)d_in[3];   // [L,1]
    const float* W_out   = (const float*)d_in[4];   // [3, N]
    const float* b_out   = (const float*)d_in[5];   // [3]
    float* y = (float*)d_out;                       // [T, 3]

    const int2* src2 = (const int2*)(ei);
    const int2* dst2 = (const int2*)(ei + EE);

    __half *hA, *hB;
    cudaGetSymbolAddress((void**)&hA, g_hA);
    cudaGetSymbolAddress((void**)&hB, g_hB);

    const int scan_blocks = (NV + 1 + SCAN_B - 1) / SCAN_B;   // 196

    // CSR build (multi-block coalesced scan — proven fast)
    zero_init_kernel<<<(NV + 255) / 256, 256>>>(b_out, y);
    hist_kernel<<<(EE / 2 + 255) / 256, 256>>>(dst2);
    scan_partial_kernel<<<scan_blocks, SCAN_B>>>();
    scan_tops_kernel<<<1, 256>>>(scan_blocks);
    scan_final_kernel<<<scan_blocks, SCAN_B>>>();
    fill_kernel<<<(EE / 2 + 255) / 256, 256>>>(src2, dst2);

    const int agg_blocks = (NV * 32 + 255) / 256;             // 8 warps/block

    // layer 0 conv (fp32 x -> fp16 h)
    conv_kernel<<<NV / 2, 256>>>(x_in, conv_w + 0 * KK, conv_b + 0, hA);
    // agg0 + conv1 fused
    agg_conv_kernel<<<agg_blocks, 256>>>((const uint2*)hA, (uint2*)hB,
                                         conv_w + 1 * KK, conv_b + 1);
    // agg1 + conv2 fused
    agg_conv_kernel<<<agg_blocks, 256>>>((const uint2*)hB, (uint2*)hA,
                                         conv_w + 2 * KK, conv_b + 2);
    // final agg -> g_xh (fp16)
    agg_final_kernel<<<agg_blocks, 256>>>((const uint2*)hA);

    // projection
    out_kernel2<<<(NV + OCHUNK - 1) / OCHUNK, 256>>>(W_out, y);
}